// round 6
// baseline (speedup 1.0000x reference)
#include <cuda_runtime.h>
#include <cuda_fp16.h>
#include <cstdint>

#define NR 8192
#define MC 8192
#define DD 64

// ---------------- device-global staging (no allocation allowed) ----------------
__device__ __align__(16) __half g_ah[NR * DD];
__device__ __align__(16) __half g_al[NR * DD];
__device__ __align__(16) __half g_bh[MC * DD];
__device__ __align__(16) __half g_bl[MC * DD];
// per-row stats: x = |p|^2, y = 2/(1-|a|^2) for a-rows, 1/(1-|b|^2) for b-rows
__device__ float2 g_apa[NR];
__device__ float2 g_bq[MC];

// ---------------- helpers ----------------
__device__ __forceinline__ float fast_sqrt(float x) {
    float r; asm("sqrt.approx.f32 %0, %1;" : "=f"(r) : "f"(x)); return r;
}
__device__ __forceinline__ float fast_lg2(float x) {
    float r; asm("lg2.approx.f32 %0, %1;" : "=f"(r) : "f"(x)); return r;
}
__device__ __forceinline__ uint32_t smem_u32(const void* p) {
    uint32_t a;
    asm("{ .reg .u64 t; cvta.to.shared.u64 t, %1; cvt.u32.u64 %0, t; }" : "=r"(a) : "l"(p));
    return a;
}
// ---- packed f32x2 (Blackwell): ptxas never auto-fuses these ----
typedef unsigned long long u64;
__device__ __forceinline__ u64 pack2(float lo, float hi) {
    u64 o; asm("mov.b64 %0, {%1, %2};" : "=l"(o) : "f"(lo), "f"(hi)); return o;
}
__device__ __forceinline__ void unpack2(float& lo, float& hi, u64 v) {
    asm("mov.b64 {%0, %1}, %2;" : "=f"(lo), "=f"(hi) : "l"(v));
}
__device__ __forceinline__ u64 add2(u64 a, u64 b) {
    u64 o; asm("add.rn.f32x2 %0, %1, %2;" : "=l"(o) : "l"(a), "l"(b)); return o;
}
__device__ __forceinline__ u64 mul2(u64 a, u64 b) {
    u64 o; asm("mul.rn.f32x2 %0, %1, %2;" : "=l"(o) : "l"(a), "l"(b)); return o;
}
__device__ __forceinline__ u64 fma2(u64 a, u64 b, u64 c) {
    u64 o; asm("fma.rn.f32x2 %0, %1, %2, %3;" : "=l"(o) : "l"(a), "l"(b), "l"(c)); return o;
}

#define CP_ASYNC16(dst, src) \
    asm volatile("cp.async.cg.shared.global [%0], [%1], 16;" :: "r"(dst), "l"(src) : "memory")
#define CP_COMMIT() asm volatile("cp.async.commit_group;" ::: "memory")
#define CP_WAIT0()  asm volatile("cp.async.wait_group 0;" ::: "memory")

#define LDSM4(R, a) \
    asm volatile("ldmatrix.sync.aligned.m8n8.x4.shared.b16 {%0,%1,%2,%3}, [%4];" \
        : "=r"((R)[0]), "=r"((R)[1]), "=r"((R)[2]), "=r"((R)[3]) : "r"(a))

#define MMA16816(d, a, b0, b1) \
    asm volatile("mma.sync.aligned.m16n8k16.row.col.f32.f16.f16.f32 " \
        "{%0,%1,%2,%3}, {%4,%5,%6,%7}, {%8,%9}, {%0,%1,%2,%3};" \
        : "+f"((d)[0]), "+f"((d)[1]), "+f"((d)[2]), "+f"((d)[3]) \
        : "r"((a)[0]), "r"((a)[1]), "r"((a)[2]), "r"((a)[3]), "r"(b0), "r"(b1))

// ---------------- prep: norms + reciprocal terms + fp16 hi/lo split ----------------
__global__ void poincare_prep_kernel(const float* __restrict__ a,
                                     const float* __restrict__ b) {
    int warp = (blockIdx.x * blockDim.x + threadIdx.x) >> 5;
    int lane = threadIdx.x & 31;
    const float* row;
    __half *dh, *dl;
    bool isA = warp < NR;
    int r = isA ? warp : warp - NR;
    if (isA) { row = a + (size_t)r * DD; dh = g_ah + (size_t)r * DD; dl = g_al + (size_t)r * DD; }
    else     { row = b + (size_t)r * DD; dh = g_bh + (size_t)r * DD; dl = g_bl + (size_t)r * DD; }

    float v0 = row[lane], v1 = row[lane + 32];
    __half h0 = __float2half_rn(v0);
    __half l0 = __float2half_rn(v0 - __half2float(h0));
    __half h1 = __float2half_rn(v1);
    __half l1 = __float2half_rn(v1 - __half2float(h1));
    dh[lane] = h0;  dh[lane + 32] = h1;
    dl[lane] = l0;  dl[lane + 32] = l1;

    float s = fmaf(v0, v0, v1 * v1);
    #pragma unroll
    for (int o = 16; o > 0; o >>= 1) s += __shfl_xor_sync(0xffffffffu, s, o);
    if (lane == 0) {
        if (isA) g_apa[r] = make_float2(s, 2.0f / (1.0f - s));
        else     g_bq[r]  = make_float2(s, 1.0f / (1.0f - s));
    }
}

// ---------------- main: fp16-split HMMA GEMM + packed-f32x2 Poincare epilogue ----------------
// CTA tile 64(M: a-rows) x 128(N: b-rows), K = 64 in one shot.
// 8 warps: warp grid 2(M) x 4(N); warp tile 32x32. 3 CTAs/SM.
#define PITCH 144
#define A_TILE_BYTES (64 * PITCH)
#define B_TILE_BYTES (128 * PITCH)
#define SMEM_TOTAL (2 * A_TILE_BYTES + 2 * B_TILE_BYTES)   // 55296

__global__ void __launch_bounds__(256, 3)
poincare_hmma_kernel(float* __restrict__ out) {
    extern __shared__ char smem[];
    char* sAh = smem;
    char* sAl = smem + A_TILE_BYTES;
    char* sBh = smem + 2 * A_TILE_BYTES;
    char* sBl = smem + 2 * A_TILE_BYTES + B_TILE_BYTES;

    const int tid = threadIdx.x;
    const int lane = tid & 31;
    const int wid = tid >> 5;
    const int wm = wid >> 2;
    const int wn = wid & 3;

    const int row0 = blockIdx.y * 64;
    const int col0 = blockIdx.x * 128;

    // ---- stage tiles via cp.async ----
    {
        const uint32_t sb = smem_u32(smem);
        #pragma unroll
        for (int t = 0; t < 2; t++) {
            int chunk = tid + 256 * t;
            int r = chunk >> 3;
            int kc = chunk & 7;
            uint32_t doff = (uint32_t)(r * PITCH + kc * 16);
            CP_ASYNC16(sb + doff, g_ah + (size_t)(row0 + r) * DD + kc * 8);
            CP_ASYNC16(sb + A_TILE_BYTES + doff, g_al + (size_t)(row0 + r) * DD + kc * 8);
        }
        #pragma unroll
        for (int t = 0; t < 4; t++) {
            int chunk = tid + 256 * t;
            int r = chunk >> 3;
            int kc = chunk & 7;
            uint32_t doff = (uint32_t)(r * PITCH + kc * 16);
            CP_ASYNC16(sb + 2 * A_TILE_BYTES + doff,
                       g_bh + (size_t)(col0 + r) * DD + kc * 8);
            CP_ASYNC16(sb + 2 * A_TILE_BYTES + B_TILE_BYTES + doff,
                       g_bl + (size_t)(col0 + r) * DD + kc * 8);
        }
        CP_COMMIT();
        CP_WAIT0();
    }
    __syncthreads();

    // ---- hoisted epilogue stats (latency hides under MMA) ----
    const int er = row0 + wm * 32 + (lane >> 2);
    const int ec = col0 + wn * 32 + 2 * (lane & 3);
    float2 rs[2][2];
    float2 cs[4][2];
    #pragma unroll
    for (int mf = 0; mf < 2; mf++) {
        rs[mf][0] = __ldg(&g_apa[er + mf * 16]);
        rs[mf][1] = __ldg(&g_apa[er + mf * 16 + 8]);
    }
    #pragma unroll
    for (int nf = 0; nf < 4; nf++) {
        cs[nf][0] = __ldg(&g_bq[ec + nf * 8]);
        cs[nf][1] = __ldg(&g_bq[ec + nf * 8 + 1]);
    }

    float acc[2][4][4];
    #pragma unroll
    for (int i = 0; i < 2; i++)
        #pragma unroll
        for (int j = 0; j < 4; j++)
            #pragma unroll
            for (int q = 0; q < 4; q++) acc[i][j][q] = 0.0f;

    const uint32_t a_row  = (uint32_t)(wm * 32 + (lane & 15));
    const uint32_t a_koff = (uint32_t)((lane >> 4) * 16);
    const uint32_t b_row  = (uint32_t)(wn * 32 + ((lane & 16) >> 1) + (lane & 7));
    const uint32_t b_koff = (uint32_t)(((lane >> 3) & 1) * 16);

    const uint32_t uAh = smem_u32(sAh), uAl = smem_u32(sAl);
    const uint32_t uBh = smem_u32(sBh), uBl = smem_u32(sBl);

    #pragma unroll
    for (int ks = 0; ks < 4; ks++) {
        const uint32_t kb = (uint32_t)(ks * 32);
        uint32_t Ah[2][4], Al[2][4];
        #pragma unroll
        for (int mf = 0; mf < 2; mf++) {
            uint32_t off = (a_row + mf * 16) * PITCH + kb + a_koff;
            LDSM4(Ah[mf], uAh + off);
            LDSM4(Al[mf], uAl + off);
        }
        uint32_t Bh[2][4], Bl[2][4];
        #pragma unroll
        for (int nh = 0; nh < 2; nh++) {
            uint32_t off = (b_row + nh * 16) * PITCH + kb + b_koff;
            LDSM4(Bh[nh], uBh + off);
            LDSM4(Bl[nh], uBl + off);
        }
        #pragma unroll
        for (int nf = 0; nf < 4; nf++) {
            uint32_t bh0 = Bh[nf >> 1][(nf & 1) * 2], bh1 = Bh[nf >> 1][(nf & 1) * 2 + 1];
            uint32_t bl0 = Bl[nf >> 1][(nf & 1) * 2], bl1 = Bl[nf >> 1][(nf & 1) * 2 + 1];
            #pragma unroll
            for (int mf = 0; mf < 2; mf++) {
                MMA16816(acc[mf][nf], Ah[mf], bh0, bh1);   // hi*hi
                MMA16816(acc[mf][nf], Ah[mf], bl0, bl1);   // hi*lo
                MMA16816(acc[mf][nf], Al[mf], bh0, bh1);   // lo*hi
            }
        }
    }

    // ---- packed f32x2 Poincare epilogue ----
    // z = sq * (ra.y * cb.y)^2 ;  y = sqrt(z) ;  res = log(1 + y + sqrt(z + 2y))
    const u64 NEG2 = pack2(-2.0f, -2.0f);
    const u64 TWO2 = pack2(2.0f, 2.0f);
    const u64 ONE2 = pack2(1.0f, 1.0f);
    const u64 LN2_2 = pack2(0.69314718056f, 0.69314718056f);

    u64 rax2[2][2], ray2b[2][2];       // {ra.x,ra.x}, {ra.y^2, ra.y^2}
    #pragma unroll
    for (int mf = 0; mf < 2; mf++)
        #pragma unroll
        for (int qh = 0; qh < 2; qh++) {
            float2 ra = rs[mf][qh];
            rax2[mf][qh]  = pack2(ra.x, ra.x);
            float r2 = ra.y * ra.y;
            ray2b[mf][qh] = pack2(r2, r2);
        }
    u64 cbx2[4], cby2q[4];             // {cb0.x,cb1.x}, {cb0.y^2, cb1.y^2}
    #pragma unroll
    for (int nf = 0; nf < 4; nf++) {
        cbx2[nf]  = pack2(cs[nf][0].x, cs[nf][1].x);
        cby2q[nf] = pack2(cs[nf][0].y * cs[nf][0].y, cs[nf][1].y * cs[nf][1].y);
    }

    #pragma unroll
    for (int mf = 0; mf < 2; mf++) {
        #pragma unroll
        for (int qh = 0; qh < 2; qh++) {          // qh=0: row er+16mf ; qh=1: +8
            #pragma unroll
            for (int nf = 0; nf < 4; nf++) {
                u64 dot2 = pack2(acc[mf][nf][2 * qh], acc[mf][nf][2 * qh + 1]);
                u64 sum2 = add2(rax2[mf][qh], cbx2[nf]);
                u64 sq2  = fma2(dot2, NEG2, sum2);          // a2+b2-2dot (pair)
                u64 z2   = mul2(mul2(sq2, ray2b[mf][qh]), cby2q[nf]);
                float z0, z1;
                unpack2(z0, z1, z2);
                z0 = fmaxf(z0, 0.0f);
                z1 = fmaxf(z1, 0.0f);
                float y0 = fast_sqrt(z0);
                float y1 = fast_sqrt(z1);
                u64 y2p = pack2(y0, y1);
                u64 tt2 = fma2(y2p, TWO2, pack2(z0, z1));   // z + 2y
                float t0, t1;
                unpack2(t0, t1, tt2);
                u64 st2 = pack2(fast_sqrt(t0), fast_sqrt(t1));
                u64 w2  = add2(add2(y2p, ONE2), st2);       // 1 + y + sqrt(z+2y)
                float w0, w1;
                unpack2(w0, w1, w2);
                u64 res2 = mul2(pack2(fast_lg2(w0), fast_lg2(w1)), LN2_2);
                size_t o = (size_t)(er + mf * 16 + qh * 8) * MC + (ec + nf * 8);
                *reinterpret_cast<u64*>(out + o) = res2;
            }
        }
    }
}

extern "C" void kernel_launch(void* const* d_in, const int* in_sizes, int n_in,
                              void* d_out, int out_size) {
    const float* a = (const float*)d_in[0];
    const float* b = (const float*)d_in[1];
    float* out = (float*)d_out;

    cudaFuncSetAttribute(poincare_hmma_kernel,
                         cudaFuncAttributeMaxDynamicSharedMemorySize, SMEM_TOTAL);

    poincare_prep_kernel<<<(NR + MC) / 8, 256>>>(a, b);
    dim3 grid(MC / 128, NR / 64);
    poincare_hmma_kernel<<<grid, 256, SMEM_TOTAL>>>(out);
}

// round 7
// speedup vs baseline: 1.0406x; 1.0406x over previous
#include <cuda_runtime.h>
#include <cuda_fp16.h>
#include <cstdint>

#define NR 8192
#define MC 8192
#define DD 64

// ---------------- device-global staging (no allocation allowed) ----------------
__device__ __align__(16) __half g_ah[NR * DD];
__device__ __align__(16) __half g_al[NR * DD];
__device__ __align__(16) __half g_bh[MC * DD];
__device__ __align__(16) __half g_bl[MC * DD];
__device__ float2 g_apa[NR];   // a-rows: {|a|^2, 2/(1-|a|^2)}
__device__ float2 g_bq[MC];    // b-rows: {|b|^2, 1/(1-|b|^2)}

// ---------------- helpers ----------------
__device__ __forceinline__ float fast_sqrt(float x) {
    float r; asm("sqrt.approx.f32 %0, %1;" : "=f"(r) : "f"(x)); return r;
}
__device__ __forceinline__ uint32_t smem_u32(const void* p) {
    uint32_t a;
    asm("{ .reg .u64 t; cvta.to.shared.u64 t, %1; cvt.u32.u64 %0, t; }" : "=r"(a) : "l"(p));
    return a;
}
#define CP_ASYNC16(dst, src) \
    asm volatile("cp.async.cg.shared.global [%0], [%1], 16;" :: "r"(dst), "l"(src) : "memory")
#define CP_COMMIT() asm volatile("cp.async.commit_group;" ::: "memory")
#define CP_WAIT0()  asm volatile("cp.async.wait_group 0;" ::: "memory")

#define LDSM4(R, a) \
    asm volatile("ldmatrix.sync.aligned.m8n8.x4.shared.b16 {%0,%1,%2,%3}, [%4];" \
        : "=r"((R)[0]), "=r"((R)[1]), "=r"((R)[2]), "=r"((R)[3]) : "r"(a))

#define MMA16816(d, a, b0, b1) \
    asm volatile("mma.sync.aligned.m16n8k16.row.col.f32.f16.f16.f32 " \
        "{%0,%1,%2,%3}, {%4,%5,%6,%7}, {%8,%9}, {%0,%1,%2,%3};" \
        : "+f"((d)[0]), "+f"((d)[1]), "+f"((d)[2]), "+f"((d)[3]) \
        : "r"((a)[0]), "r"((a)[1]), "r"((a)[2]), "r"((a)[3]), "r"(b0), "r"(b1))

// ---------------- prep: norms + reciprocal terms + fp16 hi/lo split ----------------
__global__ void poincare_prep_kernel(const float* __restrict__ a,
                                     const float* __restrict__ b) {
    int warp = (blockIdx.x * blockDim.x + threadIdx.x) >> 5;
    int lane = threadIdx.x & 31;
    const float* row;
    __half *dh, *dl;
    bool isA = warp < NR;
    int r = isA ? warp : warp - NR;
    if (isA) { row = a + (size_t)r * DD; dh = g_ah + (size_t)r * DD; dl = g_al + (size_t)r * DD; }
    else     { row = b + (size_t)r * DD; dh = g_bh + (size_t)r * DD; dl = g_bl + (size_t)r * DD; }

    float v0 = row[lane], v1 = row[lane + 32];
    __half h0 = __float2half_rn(v0);
    __half l0 = __float2half_rn(v0 - __half2float(h0));
    __half h1 = __float2half_rn(v1);
    __half l1 = __float2half_rn(v1 - __half2float(h1));
    dh[lane] = h0;  dh[lane + 32] = h1;
    dl[lane] = l0;  dl[lane + 32] = l1;

    float s = fmaf(v0, v0, v1 * v1);
    #pragma unroll
    for (int o = 16; o > 0; o >>= 1) s += __shfl_xor_sync(0xffffffffu, s, o);
    if (lane == 0) {
        if (isA) g_apa[r] = make_float2(s, 2.0f / (1.0f - s));
        else     g_bq[r]  = make_float2(s, 1.0f / (1.0f - s));
    }
}

// ---------------- main: persistent + double-buffered fp16-split HMMA ----------------
// 448 CTAs = 64 col-bands x 7 row-segments. Each CTA: B band (128 cols) resident,
// streams 18-19 A tiles (64 rows) with 2-stage cp.async pipeline.
// 8 warps: warp grid 2(M) x 4(N); warp tile 32x32. 3 CTAs/SM.
#define PITCH 144
#define BH_BYTES (128 * PITCH)            // 18432 (B hi)
#define A_HALF   (64 * PITCH)             // 9216  (A hi or lo per buffer)
#define A_BUF_BYTES (2 * A_HALF)          // 18432 per buffer
#define OFF_B   0
#define OFF_A   (2 * BH_BYTES)            // 36864
#define SMEM_TOTAL (OFF_A + 2 * A_BUF_BYTES)   // 73728 -> 3 CTAs/SM

#define SEGS 7
#define BANDS 64

__global__ void __launch_bounds__(256, 3)
poincare_hmma_kernel(float* __restrict__ out) {
    extern __shared__ char smem[];
    const uint32_t sb = smem_u32(smem);

    const int tid = threadIdx.x;
    const int lane = tid & 31;
    const int wid = tid >> 5;
    const int wm = wid >> 2;       // 0..1
    const int wn = wid & 3;        // 0..3

    const int band = blockIdx.x & 63;       // col band
    const int seg  = blockIdx.x >> 6;       // 0..6
    const int col0 = band * 128;
    const int t0   = seg * 18 + min(seg, 2);
    const int tcnt = 18 + (seg < 2 ? 1 : 0);

    // ---- load B band (hi+lo) once ----
    #pragma unroll
    for (int t = 0; t < 4; t++) {
        int chunk = tid + 256 * t;          // 0..1023
        int r = chunk >> 3;
        int kc = chunk & 7;
        uint32_t doff = (uint32_t)(r * PITCH + kc * 16);
        CP_ASYNC16(sb + OFF_B + doff,            g_bh + (size_t)(col0 + r) * DD + kc * 8);
        CP_ASYNC16(sb + OFF_B + BH_BYTES + doff, g_bl + (size_t)(col0 + r) * DD + kc * 8);
    }
    // ---- preload A tile t0 into buffer 0 ----
    {
        int row0 = t0 * 64;
        #pragma unroll
        for (int t = 0; t < 2; t++) {
            int chunk = tid + 256 * t;      // 0..511
            int r = chunk >> 3;
            int kc = chunk & 7;
            uint32_t doff = (uint32_t)(r * PITCH + kc * 16);
            CP_ASYNC16(sb + OFF_A + doff,          g_ah + (size_t)(row0 + r) * DD + kc * 8);
            CP_ASYNC16(sb + OFF_A + A_HALF + doff, g_al + (size_t)(row0 + r) * DD + kc * 8);
        }
    }
    CP_COMMIT();

    // ---- column stats: fixed for this CTA ----
    const int ec = col0 + wn * 32 + 2 * (lane & 3);
    float2 cs[4][2];
    #pragma unroll
    for (int nf = 0; nf < 4; nf++) {
        cs[nf][0] = __ldg(&g_bq[ec + nf * 8]);
        cs[nf][1] = __ldg(&g_bq[ec + nf * 8 + 1]);
    }

    // ldmatrix lane addressing (constant offsets)
    const uint32_t a_row  = (uint32_t)(wm * 32 + (lane & 15));
    const uint32_t a_koff = (uint32_t)((lane >> 4) * 16);
    const uint32_t b_row  = (uint32_t)(wn * 32 + ((lane & 16) >> 1) + (lane & 7));
    const uint32_t b_koff = (uint32_t)(((lane >> 3) & 1) * 16);
    const uint32_t uBh = sb + OFF_B;
    const uint32_t uBl = sb + OFF_B + BH_BYTES;

    for (int it = 0; it < tcnt; it++) {
        const int row0 = (t0 + it) * 64;

        CP_WAIT0();
        __syncthreads();

        // ---- prefetch next A tile into the other buffer ----
        if (it + 1 < tcnt) {
            int nrow = (t0 + it + 1) * 64;
            uint32_t abase = sb + OFF_A + ((it + 1) & 1) * A_BUF_BYTES;
            #pragma unroll
            for (int t = 0; t < 2; t++) {
                int chunk = tid + 256 * t;
                int r = chunk >> 3;
                int kc = chunk & 7;
                uint32_t doff = (uint32_t)(r * PITCH + kc * 16);
                CP_ASYNC16(abase + doff,          g_ah + (size_t)(nrow + r) * DD + kc * 8);
                CP_ASYNC16(abase + A_HALF + doff, g_al + (size_t)(nrow + r) * DD + kc * 8);
            }
            CP_COMMIT();
        }

        // ---- row stats for this tile (latency hides under MMA) ----
        const int er = row0 + wm * 32 + (lane >> 2);
        float2 rs[2][2];
        #pragma unroll
        for (int mf = 0; mf < 2; mf++) {
            rs[mf][0] = __ldg(&g_apa[er + mf * 16]);
            rs[mf][1] = __ldg(&g_apa[er + mf * 16 + 8]);
        }

        // ---- MMA over K=64 from current buffer ----
        float acc[2][4][4];
        #pragma unroll
        for (int i = 0; i < 2; i++)
            #pragma unroll
            for (int j = 0; j < 4; j++)
                #pragma unroll
                for (int q = 0; q < 4; q++) acc[i][j][q] = 0.0f;

        const uint32_t uAh = sb + OFF_A + (it & 1) * A_BUF_BYTES;
        const uint32_t uAl = uAh + A_HALF;

        #pragma unroll
        for (int ks = 0; ks < 4; ks++) {
            const uint32_t kb = (uint32_t)(ks * 32);
            uint32_t Ah[2][4], Al[2][4];
            #pragma unroll
            for (int mf = 0; mf < 2; mf++) {
                uint32_t off = (a_row + mf * 16) * PITCH + kb + a_koff;
                LDSM4(Ah[mf], uAh + off);
                LDSM4(Al[mf], uAl + off);
            }
            uint32_t Bh[2][4], Bl[2][4];
            #pragma unroll
            for (int nh = 0; nh < 2; nh++) {
                uint32_t off = (b_row + nh * 16) * PITCH + kb + b_koff;
                LDSM4(Bh[nh], uBh + off);
                LDSM4(Bl[nh], uBl + off);
            }
            #pragma unroll
            for (int nf = 0; nf < 4; nf++) {
                uint32_t bh0 = Bh[nf >> 1][(nf & 1) * 2], bh1 = Bh[nf >> 1][(nf & 1) * 2 + 1];
                uint32_t bl0 = Bl[nf >> 1][(nf & 1) * 2], bl1 = Bl[nf >> 1][(nf & 1) * 2 + 1];
                #pragma unroll
                for (int mf = 0; mf < 2; mf++) {
                    MMA16816(acc[mf][nf], Ah[mf], bh0, bh1);   // hi*hi
                    MMA16816(acc[mf][nf], Ah[mf], bl0, bl1);   // hi*lo
                    MMA16816(acc[mf][nf], Al[mf], bh0, bh1);   // lo*hi
                }
            }
        }

        // ---- fused Poincare epilogue (round-5 proven form) ----
        #pragma unroll
        for (int mf = 0; mf < 2; mf++) {
            #pragma unroll
            for (int nf = 0; nf < 4; nf++) {
                float res[4];
                #pragma unroll
                for (int q = 0; q < 4; q++) {
                    float2 ra = rs[mf][q >> 1];
                    float2 cb = cs[nf][q & 1];
                    float c  = ra.y * cb.y;
                    float sq = fmaf(-2.0f, acc[mf][nf][q], ra.x + cb.x);
                    sq = fmaxf(sq, 0.0f);
                    float y2 = (sq * c) * c;
                    float d  = fast_sqrt(sq);
                    float y  = d * c;
                    float tt = fmaf(2.0f, y, y2);
                    res[q] = __logf(1.0f + y + fast_sqrt(tt));
                }
                size_t r0 = (size_t)(er + mf * 16) * MC + (ec + nf * 8);
                *reinterpret_cast<float2*>(out + r0)          = make_float2(res[0], res[1]);
                *reinterpret_cast<float2*>(out + r0 + 8 * MC) = make_float2(res[2], res[3]);
            }
        }

        __syncthreads();   // all warps done reading current A buffer
    }
}

extern "C" void kernel_launch(void* const* d_in, const int* in_sizes, int n_in,
                              void* d_out, int out_size) {
    const float* a = (const float*)d_in[0];
    const float* b = (const float*)d_in[1];
    float* out = (float*)d_out;

    cudaFuncSetAttribute(poincare_hmma_kernel,
                         cudaFuncAttributeMaxDynamicSharedMemorySize, SMEM_TOTAL);

    poincare_prep_kernel<<<(NR + MC) / 8, 256>>>(a, b);
    poincare_hmma_kernel<<<BANDS * SEGS, 256, SMEM_TOTAL>>>(out);
}